// round 1
// baseline (speedup 1.0000x reference)
#include <cuda_runtime.h>
#include <cuda_bf16.h>
#include <cstddef>
#include <math.h>

// ---------------------------------------------------------------------------
// PCDAlign (EDVR pyramid cascading deformable alignment), fp32 direct kernels.
//   conv3_k : 3x3 conv pad1 stride1, NCHW, optional channel-concat input,
//             optional leaky-relu(0.1). smem input tile + weight tile,
//             2 horizontally adjacent pixels per thread, CO_BLK outputs/thread.
//   up2_k   : bilinear 2x upsample, align_corners=False (edge clamp), *scale.
//   dcn_k   : modulated deformable 3x3 conv, DG=8 groups, zero padding,
//             sigmoid mask, fused 64x(64*9) matvec per pixel.
// ---------------------------------------------------------------------------

#define NF 64
#define DG 8
#define KT 9

// scratch (B=4 fixed by the problem)
#define L1N (4*64*128*128)
#define L2N (4*64*64*64)
#define L3N (4*64*32*32)
#define OMN (4*216*128*128)

__device__ float g_A [L1N];
__device__ float g_B [L1N];
__device__ float g_C [L1N];
__device__ float g_D [L1N];
__device__ float g_UP[L1N];
__device__ float g_OM[OMN];
__device__ float g_L3o[L3N];
__device__ float g_L3f[L3N];
__device__ float g_L2o[L2N];
__device__ float g_L2f[L2N];

// ---------------------------------------------------------------------------
// conv3: tile 16(y) x 32(x) pixels per block, 256 threads, each thread owns
// 2 adjacent pixels. CO_BLK output channels per block (16 for Cout=64,
// 24 for Cout=216). Input channels processed in chunks of 4 via smem.
// ---------------------------------------------------------------------------
template<int CO_BLK>
__global__ __launch_bounds__(256)
void conv3_k(const float* __restrict__ in1, const float* __restrict__ in2,
             const float* __restrict__ wt,  const float* __restrict__ bs,
             float* __restrict__ out,
             int H, int W, int Cin, int C1, int Cout, int act)
{
    const int tilesX = W >> 5;
    const int tx0 = (blockIdx.x % tilesX) << 5;
    const int ty0 = (blockIdx.x / tilesX) << 4;
    const int b   = blockIdx.y;
    const int co0 = blockIdx.z * CO_BLK;
    const int tid = threadIdx.x;
    const int px  = (tid & 15) << 1;   // 0,2,...,30
    const int py  = tid >> 4;          // 0..15
    const int HW  = H * W;
    const int C2  = Cin - C1;

    __shared__ float sIn[4][18*34];
    __shared__ float sW [CO_BLK*36];

    float acc0[CO_BLK], acc1[CO_BLK];
#pragma unroll
    for (int i = 0; i < CO_BLK; i++) { acc0[i] = 0.f; acc1[i] = 0.f; }

    for (int c0 = 0; c0 < Cin; c0 += 4) {
        __syncthreads();
        // load 4 input patches (18x34 each), zero-padded at borders
        for (int idx = tid; idx < 4*18*34; idx += 256) {
            int ci = idx / (18*34);
            int r  = idx % (18*34);
            int pr = r / 34, pc = r % 34;
            int gy = ty0 - 1 + pr, gx = tx0 - 1 + pc;
            float v = 0.f;
            if ((unsigned)gy < (unsigned)H && (unsigned)gx < (unsigned)W) {
                int c = c0 + ci;
                const float* src = (c < C1)
                    ? in1 + ((size_t)b*C1 + c      ) * HW
                    : in2 + ((size_t)b*C2 + (c-C1) ) * HW;
                v = src[gy*W + gx];
            }
            sIn[ci][r] = v;
        }
        // load weights for this (co block, cin chunk): sW[co][ci][k]
        for (int idx = tid; idx < CO_BLK*36; idx += 256) {
            int co = idx / 36, rem = idx % 36;
            int ci = rem / 9, k = rem % 9;
            sW[idx] = wt[((size_t)(co0+co)*Cin + (c0+ci))*9 + k];
        }
        __syncthreads();

#pragma unroll
        for (int ci = 0; ci < 4; ci++) {
            float s[3][4];
#pragma unroll
            for (int r = 0; r < 3; r++)
#pragma unroll
                for (int c = 0; c < 4; c++)
                    s[r][c] = sIn[ci][(py + r)*34 + px + c];
#pragma unroll
            for (int co = 0; co < CO_BLK; co++) {
                const float* wp = &sW[co*36 + ci*9];
                float a0 = acc0[co], a1 = acc1[co];
#pragma unroll
                for (int kh = 0; kh < 3; kh++)
#pragma unroll
                    for (int kw = 0; kw < 3; kw++) {
                        float wv = wp[kh*3 + kw];
                        a0 += wv * s[kh][kw];
                        a1 += wv * s[kh][kw+1];
                    }
                acc0[co] = a0; acc1[co] = a1;
            }
        }
    }

    const int y = ty0 + py, x = tx0 + px;
#pragma unroll
    for (int co = 0; co < CO_BLK; co++) {
        float bv = bs[co0 + co];
        float v0 = acc0[co] + bv, v1 = acc1[co] + bv;
        if (act) {
            v0 = v0 >= 0.f ? v0 : 0.1f*v0;
            v1 = v1 >= 0.f ? v1 : 0.1f*v1;
        }
        size_t base = (((size_t)b*Cout + co0 + co)*H + y)*W + x;
        out[base]   = v0;
        out[base+1] = v1;
    }
}

// ---------------------------------------------------------------------------
// bilinear 2x upsample, align_corners=False semantics (edge clamp == jax
// renormalized triangle kernel), multiplied by scale.
// in: [N, C, H, W] -> out: [N, C, 2H, 2W]; NC folded into one dim.
// ---------------------------------------------------------------------------
__global__ void up2_k(const float* __restrict__ in, float* __restrict__ out,
                      int NC, int H, int W, float scale)
{
    const int W2 = 2*W, H2 = 2*H;
    size_t idx = (size_t)blockIdx.x * blockDim.x + threadIdx.x;
    size_t total = (size_t)NC * H2 * W2;
    if (idx >= total) return;
    int x2 = (int)(idx % W2);
    int y2 = (int)((idx / W2) % H2);
    int c  = (int)(idx / ((size_t)W2 * H2));

    float sy = (y2 + 0.5f)*0.5f - 0.5f;
    float sx = (x2 + 0.5f)*0.5f - 0.5f;
    float fy = floorf(sy), fx = floorf(sx);
    float wy = sy - fy,    wx = sx - fx;
    int y0 = (int)fy, x0 = (int)fx;
    int y0c = min(max(y0, 0), H-1), y1c = min(max(y0+1, 0), H-1);
    int x0c = min(max(x0, 0), W-1), x1c = min(max(x0+1, 0), W-1);

    const float* img = in + (size_t)c*H*W;
    float v00 = img[y0c*W + x0c];
    float v01 = img[y0c*W + x1c];
    float v10 = img[y1c*W + x0c];
    float v11 = img[y1c*W + x1c];
    float v = (1.f-wy)*((1.f-wx)*v00 + wx*v01) + wy*((1.f-wx)*v10 + wx*v11);
    out[idx] = v * scale;
}

// ---------------------------------------------------------------------------
// Modulated deformable conv (DCN_sep body, after the offset/mask conv).
//   x   : [B, 64, H, W]
//   om  : [B, 216, H, W]  (o1[0:72], o2[72:144], mask_logits[144:216])
//   wt  : [64, 64, 9]     (O, C, K)  bs: [64]
// One pixel per thread, 64 fp32 accumulators, zero-padded bilinear sampling.
// ---------------------------------------------------------------------------
__global__ __launch_bounds__(256)
void dcn_k(const float* __restrict__ x, const float* __restrict__ om,
           const float* __restrict__ wt, const float* __restrict__ bs,
           float* __restrict__ out, int H, int W, int act)
{
    const int tilesX = W >> 4;
    const int tx0 = (blockIdx.x % tilesX) << 4;
    const int ty0 = (blockIdx.x / tilesX) << 4;
    const int b   = blockIdx.y;
    const int tid = threadIdx.x;
    const int wc  = tx0 + (tid & 15);
    const int hr  = ty0 + (tid >> 4);
    const int HW  = H * W;
    const int pix = hr*W + wc;

    float acc[64];
#pragma unroll
    for (int i = 0; i < 64; i++) acc[i] = 0.f;

    const float* omb = om + (size_t)b*216*HW + pix;
    const float* xb  = x  + (size_t)b*64*HW;

    for (int g = 0; g < 8; g++) {
        const float* xg = xb + (size_t)g*8*HW;
        for (int k = 0; k < 9; k++) {
            const int gk = g*9 + k;
            float oy = __ldg(omb + (size_t)gk       *HW);
            float ox = __ldg(omb + (size_t)(72 +gk) *HW);
            float mk = __ldg(omb + (size_t)(144+gk) *HW);
            mk = 1.f / (1.f + expf(-mk));

            float py = oy + (float)(k/3 - 1) + (float)hr;
            float pv = ox + (float)(k%3 - 1) + (float)wc;
            float fy = floorf(py), fx = floorf(pv);
            float wy = py - fy,    wx = pv - fx;
            int y0 = (int)fy, x0 = (int)fx;
            int y1 = y0 + 1,  x1 = x0 + 1;
            float vy0 = (y0 >= 0 && y0 < H) ? 1.f : 0.f;
            float vy1 = (y1 >= 0 && y1 < H) ? 1.f : 0.f;
            float vx0 = (x0 >= 0 && x0 < W) ? 1.f : 0.f;
            float vx1 = (x1 >= 0 && x1 < W) ? 1.f : 0.f;
            float b00 = mk * (1.f-wy)*(1.f-wx) * vy0*vx0;
            float b01 = mk * (1.f-wy)*wx       * vy0*vx1;
            float b10 = mk * wy*(1.f-wx)       * vy1*vx0;
            float b11 = mk * wy*wx             * vy1*vx1;
            int cy0 = min(max(y0,0),H-1), cy1 = min(max(y1,0),H-1);
            int cx0 = min(max(x0,0),W-1), cx1 = min(max(x1,0),W-1);
            int o00 = cy0*W + cx0, o01 = cy0*W + cx1;
            int o10 = cy1*W + cx0, o11 = cy1*W + cx1;

            float s[8];
#pragma unroll
            for (int cc = 0; cc < 8; cc++) {
                const float* img = xg + (size_t)cc*HW;
                s[cc] = b00*__ldg(img+o00) + b01*__ldg(img+o01)
                      + b10*__ldg(img+o10) + b11*__ldg(img+o11);
            }
#pragma unroll
            for (int o = 0; o < 64; o++) {
                const float* wo = wt + ((size_t)o*64 + g*8)*9 + k;
#pragma unroll
                for (int cc = 0; cc < 8; cc++)
                    acc[o] += __ldg(wo + cc*9) * s[cc];
            }
        }
    }

#pragma unroll
    for (int o = 0; o < 64; o++) {
        float v = acc[o] + bs[o];
        if (act) v = v >= 0.f ? v : 0.1f*v;
        out[((size_t)b*64 + o)*HW + pix] = v;
    }
}

// ---------------------------------------------------------------------------
// host orchestration
// ---------------------------------------------------------------------------
static void conv3(const float* i1, const float* i2, const float* w, const float* b_,
                  float* o, int B, int H, int W, int Cin, int C1, int Cout, int act)
{
    dim3 blk(256);
    if (Cout == 216) {
        dim3 grid((W>>5)*(H>>4), B, 216/24);
        conv3_k<24><<<grid, blk>>>(i1, i2, w, b_, o, H, W, Cin, C1, Cout, act);
    } else {
        dim3 grid((W>>5)*(H>>4), B, Cout/16);
        conv3_k<16><<<grid, blk>>>(i1, i2, w, b_, o, H, W, Cin, C1, Cout, act);
    }
}

static void up2(const float* in, float* out, int B, int C, int H, int W, float scale)
{
    size_t n = (size_t)B*C*2*H*2*W;
    int blocks = (int)((n + 255) / 256);
    up2_k<<<blocks, 256>>>(in, out, B*C, H, W, scale);
}

static void dcn(const float* x, const float* om, const float* w, const float* b_,
                float* out, int B, int H, int W, int act)
{
    dim3 grid((W>>4)*(H>>4), B);
    dcn_k<<<grid, 256>>>(x, om, w, b_, out, H, W, act);
}

extern "C" void kernel_launch(void* const* d_in, const int* in_sizes, int n_in,
                              void* d_out, int out_size)
{
    const float* f1l1 = (const float*)d_in[0];
    const float* f1l2 = (const float*)d_in[1];
    const float* f1l3 = (const float*)d_in[2];
    const float* f2l1 = (const float*)d_in[3];
    const float* f2l2 = (const float*)d_in[4];
    const float* f2l3 = (const float*)d_in[5];
    const float* w128 = (const float*)d_in[6];
    const float* b128 = (const float*)d_in[7];
    const float* w64  = (const float*)d_in[8];
    const float* b64  = (const float*)d_in[9];
    const float* om_w = (const float*)d_in[10];
    const float* om_b = (const float*)d_in[11];
    const float* dw   = (const float*)d_in[12];
    const float* db   = (const float*)d_in[13];
    float* outp = (float*)d_out;

    const int B = in_sizes[0] / (NF*128*128);   // 4

    float *gA,*gB,*gC,*gD,*gUP,*gOM,*gL3o,*gL3f,*gL2o,*gL2f;
    cudaGetSymbolAddress((void**)&gA,  g_A);
    cudaGetSymbolAddress((void**)&gB,  g_B);
    cudaGetSymbolAddress((void**)&gC,  g_C);
    cudaGetSymbolAddress((void**)&gD,  g_D);
    cudaGetSymbolAddress((void**)&gUP, g_UP);
    cudaGetSymbolAddress((void**)&gOM, g_OM);
    cudaGetSymbolAddress((void**)&gL3o, g_L3o);
    cudaGetSymbolAddress((void**)&gL3f, g_L3f);
    cudaGetSymbolAddress((void**)&gL2o, g_L2o);
    cudaGetSymbolAddress((void**)&gL2f, g_L2f);

    // weight slice strides
    const size_t W128S = (size_t)64*128*9, B128S = 64;
    const size_t W64S  = (size_t)64*64*9,  B64S  = 64;
    const size_t OMWS  = (size_t)216*64*9, OMBS  = 216;
    const size_t DWS   = (size_t)64*64*9,  DBS   = 64;

    // ---- L3 (32x32) ----
    conv3(f1l3, f2l3, w128+0*W128S, b128+0*B128S, gA,  B, 32, 32, 128, 64, 64, 1);
    conv3(gA, nullptr, w64+0*W64S,  b64+0*B64S,   gL3o,B, 32, 32,  64, 64, 64, 1);
    conv3(gL3o, nullptr, om_w+0*OMWS, om_b+0*OMBS, gOM, B, 32, 32, 64, 64, 216, 0);
    dcn(f1l3, gOM, dw+0*DWS, db+0*DBS, gL3f, B, 32, 32, 1);

    // ---- L2 (64x64) ----
    conv3(f1l2, f2l2, w128+1*W128S, b128+1*B128S, gA,  B, 64, 64, 128, 64, 64, 1);
    up2(gL3o, gUP, B, 64, 32, 32, 2.0f);                       // L3_off up * 2
    conv3(gA, gUP, w128+2*W128S, b128+2*B128S, gB,  B, 64, 64, 128, 64, 64, 1);
    conv3(gB, nullptr, w64+1*W64S, b64+1*B64S, gL2o, B, 64, 64, 64, 64, 64, 1);
    conv3(gL2o, nullptr, om_w+1*OMWS, om_b+1*OMBS, gOM, B, 64, 64, 64, 64, 216, 0);
    dcn(f1l2, gOM, dw+1*DWS, db+1*DBS, gA, B, 64, 64, 0);      // L2_fea pre (no act)
    up2(gL3f, gUP, B, 64, 32, 32, 1.0f);                       // L3_fea up
    conv3(gA, gUP, w128+3*W128S, b128+3*B128S, gL2f, B, 64, 64, 128, 64, 64, 1);

    // ---- L1 (128x128) ----
    conv3(f1l1, f2l1, w128+4*W128S, b128+4*B128S, gA,  B, 128, 128, 128, 64, 64, 1);
    up2(gL2o, gUP, B, 64, 64, 64, 2.0f);                       // L2_off up * 2
    conv3(gA, gUP, w128+5*W128S, b128+5*B128S, gB,  B, 128, 128, 128, 64, 64, 1);
    conv3(gB, nullptr, w64+2*W64S, b64+2*B64S, gC,  B, 128, 128, 64, 64, 64, 1);  // L1_off
    conv3(gC, nullptr, om_w+2*OMWS, om_b+2*OMBS, gOM, B, 128, 128, 64, 64, 216, 0);
    dcn(f1l1, gOM, dw+2*DWS, db+2*DBS, gA, B, 128, 128, 0);    // L1_fea pre (no act)
    up2(gL2f, gUP, B, 64, 64, 64, 1.0f);                       // L2_fea up
    conv3(gA, gUP, w128+6*W128S, b128+6*B128S, gD,  B, 128, 128, 128, 64, 64, 0); // L1_fea

    // ---- Cascading ----
    conv3(gD, f2l1, w128+7*W128S, b128+7*B128S, gA, B, 128, 128, 128, 64, 64, 1);
    conv3(gA, nullptr, w64+3*W64S, b64+3*B64S, gB, B, 128, 128, 64, 64, 64, 1);
    conv3(gB, nullptr, om_w+3*OMWS, om_b+3*OMBS, gOM, B, 128, 128, 64, 64, 216, 0);
    dcn(gD, gOM, dw+3*DWS, db+3*DBS, outp, B, 128, 128, 1);
}